// round 8
// baseline (speedup 1.0000x reference)
#include <cuda_runtime.h>
#include <cuda_bf16.h>

#define HH 1024
#define WW 1024
#define NB 8
#define TPB 256

typedef unsigned long long u64;

// ---- packed fp32x2 helpers (sm_103a FFMA2 path, PTX-only) ----
__device__ __forceinline__ u64 pk(float lo, float hi) {
    u64 r; asm("mov.b64 %0, {%1, %2};" : "=l"(r) : "f"(lo), "f"(hi)); return r;
}
__device__ __forceinline__ void upk(u64 v, float& lo, float& hi) {
    asm("mov.b64 {%0, %1}, %2;" : "=f"(lo), "=f"(hi) : "l"(v));
}
__device__ __forceinline__ u64 fma2(u64 a, u64 b, u64 c) {
    u64 d; asm("fma.rn.f32x2 %0, %1, %2, %3;" : "=l"(d) : "l"(a), "l"(b), "l"(c));
    return d;
}

// Row buffer: 4 guard floats, 4 rows x 1024, 4 guard floats.
// Row r base = 4 + r*WW. Guards make the (never-used, masked-off) edge LDS
// at [r=0][c=-1] / [r=3][c=1024] stay in-bounds.
#define ROWBASE(r) (4 + (r) * WW)
#define SXLEN (4 * WW + 8)

__global__ void __launch_bounds__(TPB, 2)
small_sm_block_kernel(const float* __restrict__ image,
                      const float* __restrict__ x,
                      const float* __restrict__ wgt,   // (9,1,3,3)
                      const float* __restrict__ bias,  // (9,)
                      float* __restrict__ y) {
    __shared__ float sx[2][SXLEN];
    __shared__ u64 sw2[81];
    __shared__ u64 sb2[9];

    const int t = threadIdx.x;
    if (t < 81) { float w = wgt[t];  sw2[t] = pk(w, w); }
    if (t < 9)  { float b = bias[t]; sb2[t] = pk(b, b); }

    const int h0 = blockIdx.x * 2;          // output rows h0, h0+1
    const size_t plane = (size_t)HH * WW;

    // ---- cooperative load of 4 rows (h0-1..h0+2) into registers ----
    // thread t loads float4 at col 4t of each row: fully coalesced, zero waste.
    float4 v[4];
#define LDG4(SRC)                                                              \
    {                                                                          \
        _Pragma("unroll")                                                      \
        for (int k = 0; k < 4; k++) {                                          \
            int gr = h0 - 1 + k;                                               \
            if (gr >= 0 && gr < HH)                                            \
                v[k] = *reinterpret_cast<const float4*>((SRC) +                \
                        (size_t)gr * WW + 4 * t);                              \
            else                                                               \
                v[k] = make_float4(0.f, 0.f, 0.f, 0.f);                        \
        }                                                                      \
    }
#define STS4(BUF)                                                              \
    {                                                                          \
        _Pragma("unroll")                                                      \
        for (int k = 0; k < 4; k++)                                            \
            *reinterpret_cast<float4*>(&sx[(BUF)][ROWBASE(k) + 4 * t]) = v[k]; \
    }

    // ---- stage image -> buf0, build K ----
    LDG4(image);
    STS4(0);
    __syncthreads();

    // K packed vertically: KV[g][j] = (K[j]@(h0,c), K[j]@(h0+1,c)), c = t+256g
    u64 KV[4][9];
#pragma unroll
    for (int g = 0; g < 4; g++) {
        const int c = t + 256 * g;
        float raw[4][3];
#pragma unroll
        for (int r = 0; r < 4; r++)
#pragma unroll
            for (int d = 0; d < 3; d++)
                raw[r][d] = sx[0][ROWBASE(r) + c + d - 1];   // conflict-free LDS
        if (c == 0)      { raw[0][0]=0.f; raw[1][0]=0.f; raw[2][0]=0.f; raw[3][0]=0.f; }
        if (c == WW - 1) { raw[0][2]=0.f; raw[1][2]=0.f; raw[2][2]=0.f; raw[3][2]=0.f; }
        u64 p[3][3];
#pragma unroll
        for (int a = 0; a < 3; a++)
#pragma unroll
            for (int d = 0; d < 3; d++) p[a][d] = pk(raw[a][d], raw[a + 1][d]);
#pragma unroll
        for (int j = 0; j < 9; j++) {
            u64 acc = sb2[j];
#pragma unroll
            for (int a = 0; a < 3; a++)
#pragma unroll
                for (int d = 0; d < 3; d++)
                    acc = fma2(p[a][d], sw2[j * 9 + a * 3 + d], acc);
            KV[g][j] = acc;
        }
    }

    // ---- prologue: x batch 0 -> buf1 ----
    LDG4(x);
    STS4(1);

    // ---- batch loop, double-buffered: xbuf(b) = (b+1)&1 ----
#pragma unroll
    for (int b = 0; b < NB; b++) {
        __syncthreads();   // STS of x_b visible; all reads of other buf done
        const int rb = (b + 1) & 1;

        if (b + 1 < NB) LDG4(x + (size_t)(b + 1) * plane);   // prefetch in flight

#pragma unroll
        for (int g = 0; g < 4; g++) {
            const int c = t + 256 * g;
            float raw[4][3];
#pragma unroll
            for (int r = 0; r < 4; r++)
#pragma unroll
                for (int d = 0; d < 3; d++)
                    raw[r][d] = sx[rb][ROWBASE(r) + c + d - 1];
            if (c == 0)      { raw[0][0]=0.f; raw[1][0]=0.f; raw[2][0]=0.f; raw[3][0]=0.f; }
            if (c == WW - 1) { raw[0][2]=0.f; raw[1][2]=0.f; raw[2][2]=0.f; raw[3][2]=0.f; }

            u64 acc = 0ull;   // (+0.f, +0.f)
#pragma unroll
            for (int a = 0; a < 3; a++)
#pragma unroll
                for (int d = 0; d < 3; d++) {
                    u64 pr = pk(raw[a][d], raw[a + 1][d]);
                    acc = fma2(pr, KV[g][a * 3 + d], acc);
                }

            float y0, y1;
            upk(acc, y0, y1);
            float* yb = y + (size_t)b * plane + (size_t)h0 * WW + c;
            yb[0]  = y0;       // row h0   (lane-consecutive: coalesced)
            yb[WW] = y1;       // row h0+1
        }

        if (b + 1 < NB) STS4((b + 2) & 1);   // visibility via next top sync
    }
}

extern "C" void kernel_launch(void* const* d_in, const int* in_sizes, int n_in,
                              void* d_out, int out_size) {
    const float* image = (const float*)d_in[0];  // (1, 1024, 1024)
    const float* x     = (const float*)d_in[1];  // (8, 1, 1024, 1024)
    const float* klw   = (const float*)d_in[2];  // (9, 1, 3, 3)
    const float* klb   = (const float*)d_in[3];  // (9,)
    float* y = (float*)d_out;                    // (8, 1, 1024, 1024)

    small_sm_block_kernel<<<HH / 2, TPB>>>(image, x, klw, klb, y);
}

// round 9
// speedup vs baseline: 2.2713x; 2.2713x over previous
#include <cuda_runtime.h>
#include <cuda_bf16.h>

#define HH 1024
#define WW 1024
#define NB 8

// Load 6 consecutive values (cols w0-1 .. w0+4) from row hh of a (HH,WW) plane,
// with zero padding outside. One aligned LDG.128 + two predicated edge scalars.
// All three loads independent (high MLP) — no shuffles, no smem staging
// (R2/R8 showed both collapse latency hiding). All offsets are 32-bit ints to
// avoid 64-bit address-math register pairs.
__device__ __forceinline__ void load_row6(const float* __restrict__ base, int hh,
                                          int w0, float v[6]) {
    if (hh < 0 || hh >= HH) {
#pragma unroll
        for (int c = 0; c < 6; c++) v[c] = 0.0f;
        return;
    }
    const float* row = base + hh * WW;
    float4 m = *reinterpret_cast<const float4*>(row + w0);
    v[1] = m.x; v[2] = m.y; v[3] = m.z; v[4] = m.w;
    v[0] = (w0 > 0) ? row[w0 - 1] : 0.0f;
    v[5] = (w0 + 4 < WW) ? row[w0 + 4] : 0.0f;
}

__global__ void __launch_bounds__(128, 8)
small_sm_block_kernel(const float* __restrict__ image,
                      const float* __restrict__ x,
                      const float* __restrict__ wgt,   // (9,1,3,3) = 81
                      const float* __restrict__ bias,  // (9,)
                      float* __restrict__ y) {
    __shared__ float sw[81];
    __shared__ float sb[9];
    const int t = threadIdx.x;
    if (t < 81) sw[t] = wgt[t];
    if (t < 9)  sb[t] = bias[t];
    __syncthreads();

    const int h  = blockIdx.y;
    const int w0 = (blockIdx.x * 128 + t) * 4;
    const int orow = h * WW + w0;                 // fits in int

    // ---- image neighborhood: rows h-1..h+1, cols w0-1..w0+4 ----
    float img[3][6];
#pragma unroll
    for (int r = 0; r < 3; r++) load_row6(image, h - 1 + r, w0, img[r]);

    // ---- K[j][p] = bias[j] + sum_{a,d} img[a][p+d] * w[j,a,d] ----
    float K[9][4];
#pragma unroll
    for (int j = 0; j < 9; j++) {
        const float bj = sb[j];
#pragma unroll
        for (int p = 0; p < 4; p++) K[j][p] = bj;
#pragma unroll
        for (int a = 0; a < 3; a++) {
#pragma unroll
            for (int d = 0; d < 3; d++) {
                const float wv = sw[j * 9 + a * 3 + d];
#pragma unroll
                for (int p = 0; p < 4; p++) K[j][p] += img[a][p + d] * wv;
            }
        }
    }

    // ---- apply: y[b,h,w0+p] = sum_{a,d} xpad[b,h-1+a,w0+p-1+d] * K[3a+d][p] ----
#pragma unroll
    for (int b = 0; b < NB; b++) {
        const float* xb = x + b * (HH * WW);      // compile-time-constant int offset
        float xr[3][6];
#pragma unroll
        for (int r = 0; r < 3; r++) load_row6(xb, h - 1 + r, w0, xr[r]);

        float acc0 = 0.f, acc1 = 0.f, acc2 = 0.f, acc3 = 0.f;
#pragma unroll
        for (int a = 0; a < 3; a++) {
#pragma unroll
            for (int d = 0; d < 3; d++) {
                const int j = a * 3 + d;
                acc0 += xr[a][d]     * K[j][0];
                acc1 += xr[a][d + 1] * K[j][1];
                acc2 += xr[a][d + 2] * K[j][2];
                acc3 += xr[a][d + 3] * K[j][3];
            }
        }

        float4 o;
        o.x = acc0; o.y = acc1; o.z = acc2; o.w = acc3;
        *reinterpret_cast<float4*>(y + b * (HH * WW) + orow) = o;
    }
}

extern "C" void kernel_launch(void* const* d_in, const int* in_sizes, int n_in,
                              void* d_out, int out_size) {
    const float* image = (const float*)d_in[0];  // (1, 1024, 1024)
    const float* x     = (const float*)d_in[1];  // (8, 1, 1024, 1024)
    const float* klw   = (const float*)d_in[2];  // (9, 1, 3, 3)
    const float* klb   = (const float*)d_in[3];  // (9,)
    float* y = (float*)d_out;                    // (8, 1, 1024, 1024)

    dim3 block(128);
    dim3 grid(WW / 4 / 128, HH);  // (2, 1024)
    small_sm_block_kernel<<<grid, block>>>(image, x, klw, klb, y);
}

// round 10
// speedup vs baseline: 2.7112x; 1.1937x over previous
#include <cuda_runtime.h>
#include <cuda_bf16.h>

#define HH 1024
#define WW 1024
#define NB 8

// Load the 4-wide window (cols w0-1 .. w0+2) of row hh, zero-padded outside.
// One aligned LDG.64 + two predicated edge scalars; all three independent
// (preserve MLP — no shuffles / no smem staging, per R2/R7/R8). int offsets
// only (avoid 64-bit address-math register pairs).
__device__ __forceinline__ void load_row4(const float* __restrict__ base, int hh,
                                          int w0, float v[4]) {
    if (hh < 0 || hh >= HH) {
        v[0] = v[1] = v[2] = v[3] = 0.0f;
        return;
    }
    const float* row = base + hh * WW;
    float2 m = *reinterpret_cast<const float2*>(row + w0);
    v[1] = m.x; v[2] = m.y;
    v[0] = (w0 > 0) ? row[w0 - 1] : 0.0f;
    v[3] = (w0 + 2 < WW) ? row[w0 + 2] : 0.0f;
}

__global__ void __launch_bounds__(128, 7)
small_sm_block_kernel(const float* __restrict__ image,
                      const float* __restrict__ x,
                      const float* __restrict__ wgt,   // (9,1,3,3) = 81
                      const float* __restrict__ bias,  // (9,)
                      float* __restrict__ y) {
    __shared__ float sw[81];
    __shared__ float sb[9];
    const int t = threadIdx.x;
    if (t < 81) sw[t] = wgt[t];
    if (t < 9)  sb[t] = bias[t];
    __syncthreads();

    const int h0 = blockIdx.y * 2;                  // output rows h0, h0+1
    const int w0 = (blockIdx.x * 128 + t) * 2;      // output cols w0, w0+1
    const int orow = h0 * WW + w0;

    // ---- image window: 4 rows (h0-1..h0+2) x 4 cols ----
    float img[4][4];
#pragma unroll
    for (int r = 0; r < 4; r++) load_row4(image, h0 - 1 + r, w0, img[r]);

    // ---- per-pixel kernels: KA = K @ row h0 (img rows 0-2),
    //      KB = K @ row h0+1 (img rows 1-3); 2 cols each ----
    float KA[9][2], KB[9][2];
#pragma unroll
    for (int j = 0; j < 9; j++) {
        const float bj = sb[j];
        KA[j][0] = bj; KA[j][1] = bj;
        KB[j][0] = bj; KB[j][1] = bj;
#pragma unroll
        for (int a = 0; a < 3; a++) {
#pragma unroll
            for (int d = 0; d < 3; d++) {
                const float wv = sw[j * 9 + a * 3 + d];
                KA[j][0] += img[a][d]         * wv;
                KA[j][1] += img[a][d + 1]     * wv;
                KB[j][0] += img[a + 1][d]     * wv;
                KB[j][1] += img[a + 1][d + 1] * wv;
            }
        }
    }

    // ---- apply: 4 x-rows serve 2 output rows, 2 cols each ----
#pragma unroll 2
    for (int b = 0; b < NB; b++) {
        const float* xb = x + b * (HH * WW);
        float xr[4][4];
#pragma unroll
        for (int r = 0; r < 4; r++) load_row4(xb, h0 - 1 + r, w0, xr[r]);

        float a0 = 0.f, a1 = 0.f, b0 = 0.f, b1 = 0.f;
#pragma unroll
        for (int a = 0; a < 3; a++) {
#pragma unroll
            for (int d = 0; d < 3; d++) {
                const int j = a * 3 + d;
                a0 += xr[a][d]         * KA[j][0];
                a1 += xr[a][d + 1]     * KA[j][1];
                b0 += xr[a + 1][d]     * KB[j][0];
                b1 += xr[a + 1][d + 1] * KB[j][1];
            }
        }

        float* yb = y + b * (HH * WW) + orow;
        float2 oA; oA.x = a0; oA.y = a1;
        float2 oB; oB.x = b0; oB.y = b1;
        *reinterpret_cast<float2*>(yb)      = oA;   // row h0
        *reinterpret_cast<float2*>(yb + WW) = oB;   // row h0+1
    }
}

extern "C" void kernel_launch(void* const* d_in, const int* in_sizes, int n_in,
                              void* d_out, int out_size) {
    const float* image = (const float*)d_in[0];  // (1, 1024, 1024)
    const float* x     = (const float*)d_in[1];  // (8, 1, 1024, 1024)
    const float* klw   = (const float*)d_in[2];  // (9, 1, 3, 3)
    const float* klb   = (const float*)d_in[3];  // (9,)
    float* y = (float*)d_out;                    // (8, 1, 1024, 1024)

    dim3 block(128);
    dim3 grid(WW / 2 / 128, HH / 2);  // (4, 512) = 2048 blocks
    small_sm_block_kernel<<<grid, block>>>(image, x, klw, klb, y);
}